// round 3
// baseline (speedup 1.0000x reference)
#include <cuda_runtime.h>
#include <cstdint>

#define NN 50000
#define F 128
#define DEG 16

// Scratch (static device allocations are the sanctioned workaround)
__device__ float g_A[(size_t)NN * F];   // x @ Wm_top
__device__ float g_B[(size_t)NN * F];   // x @ Wm_bot
__device__ float g_xn[(size_t)NN * F];  // x + agg
__device__ float g_g[(size_t)NN * F];   // segment_sum(adj * x_new[src])

#define FMA_F32X2(d, a, b, c) \
    asm("fma.rn.f32x2 %0, %1, %2, %3;" : "=l"(d) : "l"(a), "l"(b), "l"(c))

#define UNPACK_F32X2(lo, hi, in) \
    asm("mov.b64 {%0, %1}, %2;" : "=r"(lo), "=r"(hi) : "l"(in))

// ---------------------------------------------------------------------------
// C[M,128] = X[M,128] @ W[128,128] (+bias), fp32 via packed FFMA2.
// Block 256 thr (8 warps), BM=64. Warp w owns rows w*8..w*8+7; lane l owns
// col pairs {2l,2l+1} and {64+2l,64+2l+1}.
// smem: Xs2 = X tile with every value DUPLICATED ([64][256] floats, 64KB) so
// the broadcast x-operand of FFMA2 is a single LDS.64; Ws = raw W ([128][128],
// 64KB) so the w-operand pair is a contiguous conflict-free LDS.64.
// Inner loop per k: 8 broadcast LDS.64 + 2 LDS.64 + 16 FFMA2 (no packing movs).
// ---------------------------------------------------------------------------
__global__ __launch_bounds__(256) void gemm128_f32x2_k(
    const float* __restrict__ X, const float* __restrict__ W,
    const float* __restrict__ bias, float* __restrict__ C, int M)
{
    extern __shared__ float sh[];
    float* Xs2 = sh;              // [64][256]
    float* Ws  = sh + 64 * 256;   // [128][128]

    const int tid  = threadIdx.x;
    const int lane = tid & 31;
    const int warp = tid >> 5;
    const int row0 = blockIdx.x * 64;

    // Load W into smem raw (coalesced float4 copy, 16/thread)
    {
        const float4* Wv  = (const float4*)W;
        float4*       Wsv = (float4*)Ws;
#pragma unroll
        for (int i = 0; i < 16; i++)
            Wsv[tid + i * 256] = Wv[tid + i * 256];
    }
    // Load X tile, duplicating each value: Xs2[r][2k]=Xs2[r][2k+1]=x[r][k]
    {
        const float4* Xv = (const float4*)X;
#pragma unroll
        for (int i = 0; i < 8; i++) {
            int idx = tid + i * 256;      // float4 index in the 64x128 tile
            int r   = idx >> 5;
            int c4  = idx & 31;
            float4 v = make_float4(0.f, 0.f, 0.f, 0.f);
            if (row0 + r < M) v = Xv[(size_t)(row0 + r) * 32 + c4];
            float4* dst = (float4*)&Xs2[r * 256 + c4 * 8];
            dst[0] = make_float4(v.x, v.x, v.y, v.y);
            dst[1] = make_float4(v.z, v.z, v.w, v.w);
        }
    }
    __syncthreads();

    unsigned long long acc[8][2];
#pragma unroll
    for (int i = 0; i < 8; i++) { acc[i][0] = 0ull; acc[i][1] = 0ull; }

    const int r8 = warp * 8;
    const float* xsbase = &Xs2[r8 * 256];

#pragma unroll 4
    for (int k = 0; k < 128; k++) {
        const unsigned long long w0 =
            *(const unsigned long long*)&Ws[k * 128 + 2 * lane];
        const unsigned long long w1 =
            *(const unsigned long long*)&Ws[k * 128 + 64 + 2 * lane];
#pragma unroll
        for (int i = 0; i < 8; i++) {
            const unsigned long long x2 =
                *(const unsigned long long*)&xsbase[i * 256 + 2 * k];
            FMA_F32X2(acc[i][0], x2, w0, acc[i][0]);
            FMA_F32X2(acc[i][1], x2, w1, acc[i][1]);
        }
    }

    float2 b0 = make_float2(0.f, 0.f), b1 = make_float2(0.f, 0.f);
    if (bias) {
        b0 = *(const float2*)(bias + 2 * lane);
        b1 = *(const float2*)(bias + 64 + 2 * lane);
    }
#pragma unroll
    for (int i = 0; i < 8; i++) {
        int r = row0 + r8 + i;
        if (r < M) {
            unsigned int lo, hi;
            UNPACK_F32X2(lo, hi, acc[i][0]);
            float2 o0 = make_float2(__uint_as_float(lo) + b0.x,
                                    __uint_as_float(hi) + b0.y);
            UNPACK_F32X2(lo, hi, acc[i][1]);
            float2 o1 = make_float2(__uint_as_float(lo) + b1.x,
                                    __uint_as_float(hi) + b1.y);
            *(float2*)(C + (size_t)r * 128 + 2 * lane)      = o0;
            *(float2*)(C + (size_t)r * 128 + 64 + 2 * lane) = o1;
        }
    }
}

// sigmoid via single-MUFU tanh: sigmoid(v) = 0.5*tanh(0.5v) + 0.5
__device__ __forceinline__ float sigmoidf_(float v) {
    float t;
    asm("tanh.approx.f32 %0, %1;" : "=f"(t) : "f"(0.5f * v));
    return fmaf(0.5f, t, 0.5f);
}

// ---------------------------------------------------------------------------
// Warp per node: x_new[c] = x[c] + sum_e sigmoid(A[c]+B[s_e]) * x[s_e]
// ---------------------------------------------------------------------------
__global__ __launch_bounds__(256) void edge_agg_k(
    const float* __restrict__ x, const int* __restrict__ esrc)
{
    const int gw   = (blockIdx.x * 256 + threadIdx.x) >> 5;
    const int lane = threadIdx.x & 31;
    if (gw >= NN) return;
    const int c    = gw;
    const int s_my = esrc[c * DEG + (lane & 15)];

    const float4* Bv  = (const float4*)g_B;
    const float4* xv4 = (const float4*)x;
    const float4  a   = ((const float4*)g_A)[(size_t)c * 32 + lane];
    float4 acc = make_float4(0.f, 0.f, 0.f, 0.f);

#pragma unroll
    for (int e = 0; e < DEG; e++) {
        const int    s  = __shfl_sync(0xffffffffu, s_my, e);
        const float4 b  = Bv[(size_t)s * 32 + lane];
        const float4 xs = xv4[(size_t)s * 32 + lane];
        acc.x = fmaf(sigmoidf_(a.x + b.x), xs.x, acc.x);
        acc.y = fmaf(sigmoidf_(a.y + b.y), xs.y, acc.y);
        acc.z = fmaf(sigmoidf_(a.z + b.z), xs.z, acc.z);
        acc.w = fmaf(sigmoidf_(a.w + b.w), xs.w, acc.w);
    }

    const float4 xc = xv4[(size_t)c * 32 + lane];
    float4 o = make_float4(xc.x + acc.x, xc.y + acc.y, xc.z + acc.z, xc.w + acc.w);
    ((float4*)g_xn)[(size_t)c * 32 + lane] = o;
}

// ---------------------------------------------------------------------------
// Warp per node: g[c] = sum_e adj[e] * x_new[s_e]
// ---------------------------------------------------------------------------
__global__ __launch_bounds__(256) void gather_k(
    const float* __restrict__ adj, const int* __restrict__ esrc)
{
    const int gw   = (blockIdx.x * 256 + threadIdx.x) >> 5;
    const int lane = threadIdx.x & 31;
    if (gw >= NN) return;
    const int   c    = gw;
    const int   s_my = esrc[c * DEG + (lane & 15)];
    const float a_my = adj[c * DEG + (lane & 15)];

    const float4* xnv = (const float4*)g_xn;
    float4 acc = make_float4(0.f, 0.f, 0.f, 0.f);

#pragma unroll
    for (int e = 0; e < DEG; e++) {
        const int    s  = __shfl_sync(0xffffffffu, s_my, e);
        const float  av = __shfl_sync(0xffffffffu, a_my, e);
        const float4 v  = xnv[(size_t)s * 32 + lane];
        acc.x = fmaf(av, v.x, acc.x);
        acc.y = fmaf(av, v.y, acc.y);
        acc.z = fmaf(av, v.z, acc.z);
        acc.w = fmaf(av, v.w, acc.w);
    }
    ((float4*)g_g)[(size_t)c * 32 + lane] = acc;
}

// ---------------------------------------------------------------------------
extern "C" void kernel_launch(void* const* d_in, const int* in_sizes, int n_in,
                              void* d_out, int out_size)
{
    const float* x      = (const float*)d_in[0];  // [N,128]
    const float* weight = (const float*)d_in[1];  // [128,128]
    const float* bias   = (const float*)d_in[2];  // [128]
    const float* wm     = (const float*)d_in[3];  // [256,128]
    const float* adj    = (const float*)d_in[4];  // [E]
    const int*   esrc   = (const int*)d_in[5];    // [E]
    // d_in[6] edge_dst is implicit (repeat(arange(N), DEG)) — unused
    float* out = (float*)d_out;

    void *pA, *pB, *pxn, *pg;
    cudaGetSymbolAddress(&pA,  g_A);
    cudaGetSymbolAddress(&pB,  g_B);
    cudaGetSymbolAddress(&pxn, g_xn);
    cudaGetSymbolAddress(&pg,  g_g);

    const int SMEM = (64 * 256 + 128 * 128) * 4;  // 128 KB dynamic
    static bool attr_set = false;
    if (!attr_set) {
        cudaFuncSetAttribute(gemm128_f32x2_k,
                             cudaFuncAttributeMaxDynamicSharedMemorySize, SMEM);
        attr_set = true;
    }

    const int gemm_grid = (NN + 63) / 64;   // 782
    const int warp_grid = (NN + 7) / 8;     // 6250 (8 warps/block)

    // A = x @ Wm[0:128],  B = x @ Wm[128:256]
    gemm128_f32x2_k<<<gemm_grid, 256, SMEM>>>(x, wm,             nullptr, (float*)pA, NN);
    gemm128_f32x2_k<<<gemm_grid, 256, SMEM>>>(x, wm + 128 * 128, nullptr, (float*)pB, NN);

    // x_new = x + sum_e sigmoid(A[c]+B[s]) * x[s]
    edge_agg_k<<<warp_grid, 256>>>(x, esrc);

    // g[c] = sum_e adj[e] * x_new[s]
    gather_k<<<warp_grid, 256>>>(adj, esrc);

    // out = g @ weight + bias   (linearity: commutes with the segment sum)
    gemm128_f32x2_k<<<gemm_grid, 256, SMEM>>>((const float*)pg, weight, bias, out, NN);
}

// round 6
// speedup vs baseline: 1.4368x; 1.4368x over previous
#include <cuda_runtime.h>
#include <cuda_bf16.h>
#include <cstdint>

#define NN 50000
#define DEG 16

// Scratch
__device__ float g_A[(size_t)NN * 128];   // x @ Wm_top
__device__ float g_B[(size_t)NN * 128];   // x @ Wm_bot
__device__ float g_xn[(size_t)NN * 128];  // x + agg
__device__ float g_g[(size_t)NN * 128];   // segment_sum(adj * x_new[src])

// ───────────────── tensor-core helpers (sm_80 baseline PTX) ─────────────────
__device__ __forceinline__ uint32_t smem_u32(const void* p) {
    uint32_t a;
    asm("{ .reg .u64 t; cvta.to.shared.u64 t, %1; cvt.u32.u64 %0, t; }"
        : "=r"(a) : "l"(p));
    return a;
}
__device__ __forceinline__ void ldsm_x4(uint32_t& r0, uint32_t& r1,
                                        uint32_t& r2, uint32_t& r3,
                                        uint32_t addr) {
    asm volatile("ldmatrix.sync.aligned.m8n8.x4.shared.b16 {%0,%1,%2,%3}, [%4];"
                 : "=r"(r0), "=r"(r1), "=r"(r2), "=r"(r3) : "r"(addr));
}
__device__ __forceinline__ void mma_bf16(float* c, const uint32_t* a,
                                         const uint32_t* b) {
    asm volatile(
        "mma.sync.aligned.m16n8k16.row.col.f32.bf16.bf16.f32 "
        "{%0,%1,%2,%3}, {%4,%5,%6,%7}, {%8,%9}, {%0,%1,%2,%3};"
        : "+f"(c[0]), "+f"(c[1]), "+f"(c[2]), "+f"(c[3])
        : "r"(a[0]), "r"(a[1]), "r"(a[2]), "r"(a[3]), "r"(b[0]), "r"(b[1]));
}

// Padded bf16 tile: 128 rows x 136 halves (272 B row stride).
// 272r % 128 = 16r % 128 -> rows of each 8-row ldmatrix group hit distinct
// 16B banks: conflict-free LDSM.
#define TSTRIDE 136
#define TILE_BYTES (128 * TSTRIDE * 2)  // 34816
#define SM_TOTAL (4 * TILE_BYTES)       // Ahi|Alo|Bhi|Blo = 139264 B

__device__ __forceinline__ void cvt_pair(float v, __nv_bfloat16& h, __nv_bfloat16& l) {
    h = __float2bfloat16_rn(v);
    l = __float2bfloat16_rn(v - (float)h);
}

// ---------------------------------------------------------------------------
// C[M,128] = X[M,128] @ W[128,128] (+bias) via mma.sync bf16, 3-pass split:
// C = Xhi*Whi + Xhi*Wlo + Xlo*Whi  (fp32 register accumulators)
// Block 256 thr (8 warps); warp tile 32(M) x 64(N); K=128 resident in smem.
// ---------------------------------------------------------------------------
__global__ __launch_bounds__(256) void tc_gemm_k(
    const float* __restrict__ X, const float* __restrict__ W,
    const float* __restrict__ bias, float* __restrict__ C, int M)
{
    extern __shared__ char sh[];
    __nv_bfloat16* Ahi = (__nv_bfloat16*)(sh);
    __nv_bfloat16* Alo = (__nv_bfloat16*)(sh + TILE_BYTES);
    __nv_bfloat16* Bhi = (__nv_bfloat16*)(sh + 2 * TILE_BYTES);
    __nv_bfloat16* Blo = (__nv_bfloat16*)(sh + 3 * TILE_BYTES);

    const int tid  = threadIdx.x;
    const int lane = tid & 31;
    const int wid  = tid >> 5;
    const int row0 = blockIdx.x * 128;

    // ---- load + split-convert operands into smem ----
    if (tid < 128) {
        // A row r = tid: X[row0+r][0:128]
        const int r = tid;
        const bool valid = (row0 + r) < M;
        const float4* Xr = (const float4*)(X + (size_t)(row0 + r) * 128);
#pragma unroll 8
        for (int k = 0; k < 128; k += 4) {
            float4 v = valid ? Xr[k >> 2] : make_float4(0.f, 0.f, 0.f, 0.f);
            __nv_bfloat16 h0, l0, h1, l1, h2, l2, h3, l3;
            cvt_pair(v.x, h0, l0); cvt_pair(v.y, h1, l1);
            cvt_pair(v.z, h2, l2); cvt_pair(v.w, h3, l3);
            __nv_bfloat162 hA = {h0, h1}, hB = {h2, h3};
            __nv_bfloat162 lA = {l0, l1}, lB = {l2, l3};
            *(uint2*)&Ahi[r * TSTRIDE + k] = make_uint2(*(uint32_t*)&hA, *(uint32_t*)&hB);
            *(uint2*)&Alo[r * TSTRIDE + k] = make_uint2(*(uint32_t*)&lA, *(uint32_t*)&lB);
        }
    } else {
        // B row n = tid-128: W^T[n][k] = W[k][n] (coalesced across the warp per k)
        const int n = tid - 128;
#pragma unroll 4
        for (int k = 0; k < 128; k += 4) {
            float4 v = make_float4(W[(k + 0) * 128 + n], W[(k + 1) * 128 + n],
                                   W[(k + 2) * 128 + n], W[(k + 3) * 128 + n]);
            __nv_bfloat16 h0, l0, h1, l1, h2, l2, h3, l3;
            cvt_pair(v.x, h0, l0); cvt_pair(v.y, h1, l1);
            cvt_pair(v.z, h2, l2); cvt_pair(v.w, h3, l3);
            __nv_bfloat162 hA = {h0, h1}, hB = {h2, h3};
            __nv_bfloat162 lA = {l0, l1}, lB = {l2, l3};
            *(uint2*)&Bhi[n * TSTRIDE + k] = make_uint2(*(uint32_t*)&hA, *(uint32_t*)&hB);
            *(uint2*)&Blo[n * TSTRIDE + k] = make_uint2(*(uint32_t*)&lA, *(uint32_t*)&lB);
        }
    }
    __syncthreads();

    // ---- mma mainloop ----
    const int mr = (wid & 3) * 32;   // warp M offset
    const int nc = (wid >> 2) * 64;  // warp N offset

    float acc[2][8][4];
#pragma unroll
    for (int tm = 0; tm < 2; tm++)
#pragma unroll
        for (int j = 0; j < 8; j++)
#pragma unroll
            for (int q = 0; q < 4; q++) acc[tm][j][q] = 0.f;

    const uint32_t sb = smem_u32(sh);
    // per-lane ldmatrix base offsets (halves -> bytes)
    const uint32_t a_lane = ((lane & 15) * TSTRIDE + (lane >> 4) * 8) * 2;
    const uint32_t sA[2] = { sb + (uint32_t)(mr * TSTRIDE * 2) + a_lane,
                             sb + (uint32_t)((mr + 16) * TSTRIDE * 2) + a_lane };
    const uint32_t sB[4] = { sb + 2 * TILE_BYTES + (uint32_t)(nc * TSTRIDE * 2) + a_lane,
                             sb + 2 * TILE_BYTES + (uint32_t)((nc + 16) * TSTRIDE * 2) + a_lane,
                             sb + 2 * TILE_BYTES + (uint32_t)((nc + 32) * TSTRIDE * 2) + a_lane,
                             sb + 2 * TILE_BYTES + (uint32_t)((nc + 48) * TSTRIDE * 2) + a_lane };

    // pass p: A from {hi,hi,lo}, B from {hi,lo,hi}
    const uint32_t aoff[3] = { 0u, 0u, (uint32_t)TILE_BYTES };
    const uint32_t boff[3] = { 0u, (uint32_t)TILE_BYTES, 0u };

#pragma unroll 1
    for (int p = 0; p < 3; p++) {
#pragma unroll
        for (int kk = 0; kk < 8; kk++) {
            const uint32_t kb = kk * 32;  // 16 halves = 32 bytes
            uint32_t a[2][4];
            ldsm_x4(a[0][0], a[0][1], a[0][2], a[0][3], sA[0] + aoff[p] + kb);
            ldsm_x4(a[1][0], a[1][1], a[1][2], a[1][3], sA[1] + aoff[p] + kb);
            uint32_t b[8][2];
#pragma unroll
            for (int jp = 0; jp < 4; jp++) {
                uint32_t m0, m1, m2, m3;
                ldsm_x4(m0, m1, m2, m3, sB[jp] + boff[p] + kb);
                b[2 * jp][0] = m0; b[2 * jp][1] = m2;      // n-tile jp*2
                b[2 * jp + 1][0] = m1; b[2 * jp + 1][1] = m3;  // n-tile jp*2+1
            }
#pragma unroll
            for (int tm = 0; tm < 2; tm++)
#pragma unroll
                for (int j = 0; j < 8; j++)
                    mma_bf16(acc[tm][j], a[tm], b[j]);
        }
    }

    // ---- epilogue: registers -> C ----
#pragma unroll
    for (int j = 0; j < 8; j++) {
        const int col = nc + j * 8 + (lane & 3) * 2;
        float2 bv = make_float2(0.f, 0.f);
        if (bias) bv = *(const float2*)(bias + col);
#pragma unroll
        for (int tm = 0; tm < 2; tm++) {
            const int ra = row0 + mr + tm * 16 + (lane >> 2);
            const int rb = ra + 8;
            if (ra < M)
                *(float2*)(C + (size_t)ra * 128 + col) =
                    make_float2(acc[tm][j][0] + bv.x, acc[tm][j][1] + bv.y);
            if (rb < M)
                *(float2*)(C + (size_t)rb * 128 + col) =
                    make_float2(acc[tm][j][2] + bv.x, acc[tm][j][3] + bv.y);
        }
    }
}

// sigmoid via single-MUFU tanh: sigmoid(v) = 0.5*tanh(0.5v) + 0.5
__device__ __forceinline__ float sigmoidf_(float v) {
    float t;
    asm("tanh.approx.f32 %0, %1;" : "=f"(t) : "f"(0.5f * v));
    return fmaf(0.5f, t, 0.5f);
}

// ---------------------------------------------------------------------------
// Warp per node: x_new[c] = x[c] + sum_e sigmoid(A[c]+B[s_e]) * x[s_e]
// ---------------------------------------------------------------------------
__global__ __launch_bounds__(256) void edge_agg_k(
    const float* __restrict__ x, const int* __restrict__ esrc)
{
    const int gw   = (blockIdx.x * 256 + threadIdx.x) >> 5;
    const int lane = threadIdx.x & 31;
    if (gw >= NN) return;
    const int c    = gw;
    const int s_my = esrc[c * DEG + (lane & 15)];

    const float4* Bv  = (const float4*)g_B;
    const float4* xv4 = (const float4*)x;
    const float4  a   = ((const float4*)g_A)[(size_t)c * 32 + lane];
    float4 acc = make_float4(0.f, 0.f, 0.f, 0.f);

#pragma unroll
    for (int e = 0; e < DEG; e++) {
        const int    s  = __shfl_sync(0xffffffffu, s_my, e);
        const float4 b  = Bv[(size_t)s * 32 + lane];
        const float4 xs = xv4[(size_t)s * 32 + lane];
        acc.x = fmaf(sigmoidf_(a.x + b.x), xs.x, acc.x);
        acc.y = fmaf(sigmoidf_(a.y + b.y), xs.y, acc.y);
        acc.z = fmaf(sigmoidf_(a.z + b.z), xs.z, acc.z);
        acc.w = fmaf(sigmoidf_(a.w + b.w), xs.w, acc.w);
    }

    const float4 xc = xv4[(size_t)c * 32 + lane];
    float4 o = make_float4(xc.x + acc.x, xc.y + acc.y, xc.z + acc.z, xc.w + acc.w);
    ((float4*)g_xn)[(size_t)c * 32 + lane] = o;
}

// ---------------------------------------------------------------------------
// Warp per node: g[c] = sum_e adj[e] * x_new[s_e]
// ---------------------------------------------------------------------------
__global__ __launch_bounds__(256) void gather_k(
    const float* __restrict__ adj, const int* __restrict__ esrc)
{
    const int gw   = (blockIdx.x * 256 + threadIdx.x) >> 5;
    const int lane = threadIdx.x & 31;
    if (gw >= NN) return;
    const int   c    = gw;
    const int   s_my = esrc[c * DEG + (lane & 15)];
    const float a_my = adj[c * DEG + (lane & 15)];

    const float4* xnv = (const float4*)g_xn;
    float4 acc = make_float4(0.f, 0.f, 0.f, 0.f);

#pragma unroll
    for (int e = 0; e < DEG; e++) {
        const int    s  = __shfl_sync(0xffffffffu, s_my, e);
        const float  av = __shfl_sync(0xffffffffu, a_my, e);
        const float4 v  = xnv[(size_t)s * 32 + lane];
        acc.x = fmaf(av, v.x, acc.x);
        acc.y = fmaf(av, v.y, acc.y);
        acc.z = fmaf(av, v.z, acc.z);
        acc.w = fmaf(av, v.w, acc.w);
    }
    ((float4*)g_g)[(size_t)c * 32 + lane] = acc;
}

// ---------------------------------------------------------------------------
extern "C" void kernel_launch(void* const* d_in, const int* in_sizes, int n_in,
                              void* d_out, int out_size)
{
    const float* x      = (const float*)d_in[0];  // [N,128]
    const float* weight = (const float*)d_in[1];  // [128,128]
    const float* bias   = (const float*)d_in[2];  // [128]
    const float* wm     = (const float*)d_in[3];  // [256,128]
    const float* adj    = (const float*)d_in[4];  // [E]
    const int*   esrc   = (const int*)d_in[5];    // [E]
    float* out = (float*)d_out;

    void *pA, *pB, *pxn, *pg;
    cudaGetSymbolAddress(&pA,  g_A);
    cudaGetSymbolAddress(&pB,  g_B);
    cudaGetSymbolAddress(&pxn, g_xn);
    cudaGetSymbolAddress(&pg,  g_g);

    cudaFuncSetAttribute(tc_gemm_k, cudaFuncAttributeMaxDynamicSharedMemorySize,
                         SM_TOTAL);

    const int gemm_grid = (NN + 127) / 128;  // 391
    const int warp_grid = (NN + 7) / 8;      // 6250

    // A = x @ Wm[0:128],  B = x @ Wm[128:256]
    tc_gemm_k<<<gemm_grid, 256, SM_TOTAL>>>(x, wm,             nullptr, (float*)pA, NN);
    tc_gemm_k<<<gemm_grid, 256, SM_TOTAL>>>(x, wm + 128 * 128, nullptr, (float*)pB, NN);

    // x_new = x + sum_e sigmoid(A[c]+B[s]) * x[s]
    edge_agg_k<<<warp_grid, 256>>>(x, esrc);

    // g[c] = sum_e adj[e] * x_new[s]
    gather_k<<<warp_grid, 256>>>(adj, esrc);

    // out = g @ weight + bias   (linearity: commutes with the segment sum)
    tc_gemm_k<<<gemm_grid, 256, SM_TOTAL>>>((const float*)pg, weight, bias, out, NN);
}

// round 8
// speedup vs baseline: 1.6723x; 1.1639x over previous
#include <cuda_runtime.h>
#include <cuda_bf16.h>
#include <cuda_fp16.h>
#include <cstdint>

#define NN 50000
#define DEG 16

// Scratch
__device__ float g_A[(size_t)NN * 128];    // x @ Wm_top (fp32)
__device__ uint4 g_bx[(size_t)NN * 32];    // packed per node: 32 quads of
                                           // [B fp16 x4 | x fp16 x4] (16 B)
__device__ uint2 g_xnh[(size_t)NN * 32];   // x_new fp16 (4 halves per uint2)
__device__ float g_g[(size_t)NN * 128];    // segment_sum(adj * x_new[src])

// ───────────────── tensor-core helpers (sm_80 baseline PTX) ─────────────────
__device__ __forceinline__ uint32_t smem_u32(const void* p) {
    uint32_t a;
    asm("{ .reg .u64 t; cvta.to.shared.u64 t, %1; cvt.u32.u64 %0, t; }"
        : "=r"(a) : "l"(p));
    return a;
}
__device__ __forceinline__ void ldsm_x4(uint32_t& r0, uint32_t& r1,
                                        uint32_t& r2, uint32_t& r3,
                                        uint32_t addr) {
    asm volatile("ldmatrix.sync.aligned.m8n8.x4.shared.b16 {%0,%1,%2,%3}, [%4];"
                 : "=r"(r0), "=r"(r1), "=r"(r2), "=r"(r3) : "r"(addr));
}
__device__ __forceinline__ void mma_bf16(float* c, const uint32_t* a,
                                         const uint32_t* b) {
    asm volatile(
        "mma.sync.aligned.m16n8k16.row.col.f32.bf16.bf16.f32 "
        "{%0,%1,%2,%3}, {%4,%5,%6,%7}, {%8,%9}, {%0,%1,%2,%3};"
        : "+f"(c[0]), "+f"(c[1]), "+f"(c[2]), "+f"(c[3])
        : "r"(a[0]), "r"(a[1]), "r"(a[2]), "r"(a[3]), "r"(b[0]), "r"(b[1]));
}

#define TSTRIDE 136
#define TILE_BYTES (128 * TSTRIDE * 2)  // 34816
#define SM_TOTAL (4 * TILE_BYTES)       // 139264 B

__device__ __forceinline__ void cvt_pair(float v, __nv_bfloat16& h, __nv_bfloat16& l) {
    h = __float2bfloat16_rn(v);
    l = __float2bfloat16_rn(v - (float)h);
}

// ===========================================================================
// Shared GEMM core: computes the 128x128 tile product into acc via the
// 3-pass bf16 split. Caller handles the epilogue.
// ===========================================================================
struct GemmCtx {
    float acc[2][8][4];
    int mr, nc;
};

__device__ __forceinline__ void gemm_core(
    char* sh, const float* __restrict__ X, const float* __restrict__ W,
    int row0, int M, GemmCtx& g, bool pack_x /* also write x fp16 to g_bx */)
{
    __nv_bfloat16* Ahi = (__nv_bfloat16*)(sh);
    __nv_bfloat16* Alo = (__nv_bfloat16*)(sh + TILE_BYTES);
    __nv_bfloat16* Bhi = (__nv_bfloat16*)(sh + 2 * TILE_BYTES);
    __nv_bfloat16* Blo = (__nv_bfloat16*)(sh + 3 * TILE_BYTES);

    const int tid  = threadIdx.x;
    const int lane = tid & 31;
    const int wid  = tid >> 5;

    if (tid < 128) {
        const int r = tid;
        const bool valid = (row0 + r) < M;
        const float4* Xr = (const float4*)(X + (size_t)(row0 + r) * 128);
#pragma unroll 8
        for (int k = 0; k < 128; k += 4) {
            float4 v = valid ? Xr[k >> 2] : make_float4(0.f, 0.f, 0.f, 0.f);
            __nv_bfloat16 h0, l0, h1, l1, h2, l2, h3, l3;
            cvt_pair(v.x, h0, l0); cvt_pair(v.y, h1, l1);
            cvt_pair(v.z, h2, l2); cvt_pair(v.w, h3, l3);
            __nv_bfloat162 hA = {h0, h1}, hB = {h2, h3};
            __nv_bfloat162 lA = {l0, l1}, lB = {l2, l3};
            *(uint2*)&Ahi[r * TSTRIDE + k] = make_uint2(*(uint32_t*)&hA, *(uint32_t*)&hB);
            *(uint2*)&Alo[r * TSTRIDE + k] = make_uint2(*(uint32_t*)&lA, *(uint32_t*)&lB);
            if (pack_x && valid) {
                __half2 x01 = __floats2half2_rn(v.x, v.y);
                __half2 x23 = __floats2half2_rn(v.z, v.w);
                *(uint2*)((char*)&g_bx[(size_t)(row0 + r) * 32 + (k >> 2)] + 8) =
                    make_uint2(*(uint32_t*)&x01, *(uint32_t*)&x23);
            }
        }
    } else {
        const int n = tid - 128;
#pragma unroll 4
        for (int k = 0; k < 128; k += 4) {
            float4 v = make_float4(W[(k + 0) * 128 + n], W[(k + 1) * 128 + n],
                                   W[(k + 2) * 128 + n], W[(k + 3) * 128 + n]);
            __nv_bfloat16 h0, l0, h1, l1, h2, l2, h3, l3;
            cvt_pair(v.x, h0, l0); cvt_pair(v.y, h1, l1);
            cvt_pair(v.z, h2, l2); cvt_pair(v.w, h3, l3);
            __nv_bfloat162 hA = {h0, h1}, hB = {h2, h3};
            __nv_bfloat162 lA = {l0, l1}, lB = {l2, l3};
            *(uint2*)&Bhi[n * TSTRIDE + k] = make_uint2(*(uint32_t*)&hA, *(uint32_t*)&hB);
            *(uint2*)&Blo[n * TSTRIDE + k] = make_uint2(*(uint32_t*)&lA, *(uint32_t*)&lB);
        }
    }
    __syncthreads();

    g.mr = (wid & 3) * 32;
    g.nc = (wid >> 2) * 64;
#pragma unroll
    for (int tm = 0; tm < 2; tm++)
#pragma unroll
        for (int j = 0; j < 8; j++)
#pragma unroll
            for (int q = 0; q < 4; q++) g.acc[tm][j][q] = 0.f;

    const uint32_t sb = smem_u32(sh);
    const uint32_t a_lane = ((lane & 15) * TSTRIDE + (lane >> 4) * 8) * 2;
    const uint32_t sA[2] = { sb + (uint32_t)(g.mr * TSTRIDE * 2) + a_lane,
                             sb + (uint32_t)((g.mr + 16) * TSTRIDE * 2) + a_lane };
    const uint32_t sB[4] = {
        sb + 2 * TILE_BYTES + (uint32_t)(g.nc * TSTRIDE * 2) + a_lane,
        sb + 2 * TILE_BYTES + (uint32_t)((g.nc + 16) * TSTRIDE * 2) + a_lane,
        sb + 2 * TILE_BYTES + (uint32_t)((g.nc + 32) * TSTRIDE * 2) + a_lane,
        sb + 2 * TILE_BYTES + (uint32_t)((g.nc + 48) * TSTRIDE * 2) + a_lane };

    const uint32_t aoff[3] = { 0u, 0u, (uint32_t)TILE_BYTES };
    const uint32_t boff[3] = { 0u, (uint32_t)TILE_BYTES, 0u };

#pragma unroll 1
    for (int p = 0; p < 3; p++) {
#pragma unroll
        for (int kk = 0; kk < 8; kk++) {
            const uint32_t kb = kk * 32;
            uint32_t a[2][4];
            ldsm_x4(a[0][0], a[0][1], a[0][2], a[0][3], sA[0] + aoff[p] + kb);
            ldsm_x4(a[1][0], a[1][1], a[1][2], a[1][3], sA[1] + aoff[p] + kb);
            uint32_t b[8][2];
#pragma unroll
            for (int jp = 0; jp < 4; jp++) {
                uint32_t m0, m1, m2, m3;
                ldsm_x4(m0, m1, m2, m3, sB[jp] + boff[p] + kb);
                b[2 * jp][0] = m0; b[2 * jp][1] = m2;
                b[2 * jp + 1][0] = m1; b[2 * jp + 1][1] = m3;
            }
#pragma unroll
            for (int tm = 0; tm < 2; tm++)
#pragma unroll
                for (int j = 0; j < 8; j++)
                    mma_bf16(g.acc[tm][j], a[tm], b[j]);
        }
    }
}

// ---------------------------------------------------------------------------
// Fused Wm GEMM: grid (tiles, 2). y=0: A = x@Wm_top -> g_A fp32 (+ pack x fp16)
//                                y=1: B = x@Wm_bot -> packed fp16 in g_bx
// ---------------------------------------------------------------------------
__global__ __launch_bounds__(256) void wm_gemm_k(
    const float* __restrict__ X, const float* __restrict__ wm, int M)
{
    extern __shared__ char sh[];
    const int row0 = blockIdx.x * 128;
    const int half = blockIdx.y;
    GemmCtx g;
    gemm_core(sh, X, wm + (size_t)half * 128 * 128, row0, M, g, half == 0);

    const int lane = threadIdx.x & 31;
#pragma unroll
    for (int j = 0; j < 8; j++) {
        const int col = g.nc + j * 8 + (lane & 3) * 2;
#pragma unroll
        for (int tm = 0; tm < 2; tm++) {
            const int ra = row0 + g.mr + tm * 16 + (lane >> 2);
            const int rb = ra + 8;
            if (half == 0) {
                if (ra < M)
                    *(float2*)(g_A + (size_t)ra * 128 + col) =
                        make_float2(g.acc[tm][j][0], g.acc[tm][j][1]);
                if (rb < M)
                    *(float2*)(g_A + (size_t)rb * 128 + col) =
                        make_float2(g.acc[tm][j][2], g.acc[tm][j][3]);
            } else {
                const uint32_t off = (uint32_t)((col >> 2) * 16 + (col & 3) * 2);
                if (ra < M) {
                    __half2 h = __floats2half2_rn(g.acc[tm][j][0], g.acc[tm][j][1]);
                    *(uint32_t*)((char*)&g_bx[(size_t)ra * 32] + off) = *(uint32_t*)&h;
                }
                if (rb < M) {
                    __half2 h = __floats2half2_rn(g.acc[tm][j][2], g.acc[tm][j][3]);
                    *(uint32_t*)((char*)&g_bx[(size_t)rb * 32] + off) = *(uint32_t*)&h;
                }
            }
        }
    }
}

// ---------------------------------------------------------------------------
// Final GEMM: out = g_g @ weight + bias (fp32 in/out)
// ---------------------------------------------------------------------------
__global__ __launch_bounds__(256) void tc_gemm_k(
    const float* __restrict__ X, const float* __restrict__ W,
    const float* __restrict__ bias, float* __restrict__ C, int M)
{
    extern __shared__ char sh[];
    const int row0 = blockIdx.x * 128;
    GemmCtx g;
    gemm_core(sh, X, W, row0, M, g, false);

    const int lane = threadIdx.x & 31;
#pragma unroll
    for (int j = 0; j < 8; j++) {
        const int col = g.nc + j * 8 + (lane & 3) * 2;
        const float2 bv = *(const float2*)(bias + col);
#pragma unroll
        for (int tm = 0; tm < 2; tm++) {
            const int ra = row0 + g.mr + tm * 16 + (lane >> 2);
            const int rb = ra + 8;
            if (ra < M)
                *(float2*)(C + (size_t)ra * 128 + col) =
                    make_float2(g.acc[tm][j][0] + bv.x, g.acc[tm][j][1] + bv.y);
            if (rb < M)
                *(float2*)(C + (size_t)rb * 128 + col) =
                    make_float2(g.acc[tm][j][2] + bv.x, g.acc[tm][j][3] + bv.y);
        }
    }
}

__device__ __forceinline__ float sig_t(float half_arg) {
    // sigmoid(2*half_arg) = 0.5*tanh(half_arg) + 0.5
    float t;
    asm("tanh.approx.f32 %0, %1;" : "=f"(t) : "f"(half_arg));
    return fmaf(0.5f, t, 0.5f);
}

// ---------------------------------------------------------------------------
// Warp per node: x_new[c] = x[c] + sum_e sigmoid(A[c]+B[s]) * x[s]
// One LDG.128 per lane per edge from the packed [B fp16|x fp16] record.
// Output x_new as fp16.
// ---------------------------------------------------------------------------
__global__ __launch_bounds__(256) void edge_agg_k(
    const float* __restrict__ x, const int* __restrict__ esrc)
{
    const int gw   = (blockIdx.x * 256 + threadIdx.x) >> 5;
    const int lane = threadIdx.x & 31;
    if (gw >= NN) return;
    const int c    = gw;
    const int s_my = esrc[c * DEG + (lane & 15)];

    const float4 a = ((const float4*)g_A)[(size_t)c * 32 + lane];
    const __half2 h05  = __floats2half2_rn(0.5f, 0.5f);
    const __half2 ha01 = __floats2half2_rn(0.5f * a.x, 0.5f * a.y);
    const __half2 ha23 = __floats2half2_rn(0.5f * a.z, 0.5f * a.w);

    float4 acc = make_float4(0.f, 0.f, 0.f, 0.f);

#pragma unroll
    for (int e = 0; e < DEG; e++) {
        const int   s = __shfl_sync(0xffffffffu, s_my, e);
        const uint4 p = g_bx[(size_t)s * 32 + lane];
        const __half2 b01 = *(const __half2*)&p.x;
        const __half2 b23 = *(const __half2*)&p.y;
        // half-arg = 0.5*(A+B)
        const float2 h01 = __half22float2(__hfma2(b01, h05, ha01));
        const float2 h23 = __half22float2(__hfma2(b23, h05, ha23));
        const float2 xf01 = __half22float2(*(const __half2*)&p.z);
        const float2 xf23 = __half22float2(*(const __half2*)&p.w);
        acc.x = fmaf(sig_t(h01.x), xf01.x, acc.x);
        acc.y = fmaf(sig_t(h01.y), xf01.y, acc.y);
        acc.z = fmaf(sig_t(h23.x), xf23.x, acc.z);
        acc.w = fmaf(sig_t(h23.y), xf23.y, acc.w);
    }

    const float4 xc = ((const float4*)x)[(size_t)c * 32 + lane];
    __half2 o01 = __floats2half2_rn(xc.x + acc.x, xc.y + acc.y);
    __half2 o23 = __floats2half2_rn(xc.z + acc.z, xc.w + acc.w);
    g_xnh[(size_t)c * 32 + lane] = make_uint2(*(uint32_t*)&o01, *(uint32_t*)&o23);
}

// ---------------------------------------------------------------------------
// Warp per node: g[c] = sum_e adj[e] * x_new_fp16[s_e]  (fp32 out)
// ---------------------------------------------------------------------------
__global__ __launch_bounds__(256) void gather_k(
    const float* __restrict__ adj, const int* __restrict__ esrc)
{
    const int gw   = (blockIdx.x * 256 + threadIdx.x) >> 5;
    const int lane = threadIdx.x & 31;
    if (gw >= NN) return;
    const int   c    = gw;
    const int   s_my = esrc[c * DEG + (lane & 15)];
    const float a_my = adj[c * DEG + (lane & 15)];

    float4 acc = make_float4(0.f, 0.f, 0.f, 0.f);

#pragma unroll
    for (int e = 0; e < DEG; e++) {
        const int   s  = __shfl_sync(0xffffffffu, s_my, e);
        const float av = __shfl_sync(0xffffffffu, a_my, e);
        const uint2 p  = g_xnh[(size_t)s * 32 + lane];
        const float2 v01 = __half22float2(*(const __half2*)&p.x);
        const float2 v23 = __half22float2(*(const __half2*)&p.y);
        acc.x = fmaf(av, v01.x, acc.x);
        acc.y = fmaf(av, v01.y, acc.y);
        acc.z = fmaf(av, v23.x, acc.z);
        acc.w = fmaf(av, v23.y, acc.w);
    }
    ((float4*)g_g)[(size_t)c * 32 + lane] = acc;
}

// ---------------------------------------------------------------------------
extern "C" void kernel_launch(void* const* d_in, const int* in_sizes, int n_in,
                              void* d_out, int out_size)
{
    const float* x      = (const float*)d_in[0];  // [N,128]
    const float* weight = (const float*)d_in[1];  // [128,128]
    const float* bias   = (const float*)d_in[2];  // [128]
    const float* wm     = (const float*)d_in[3];  // [256,128]
    const float* adj    = (const float*)d_in[4];  // [E]
    const int*   esrc   = (const int*)d_in[5];    // [E]
    float* out = (float*)d_out;

    void* pg;
    cudaGetSymbolAddress(&pg, g_g);

    cudaFuncSetAttribute(wm_gemm_k, cudaFuncAttributeMaxDynamicSharedMemorySize,
                         SM_TOTAL);
    cudaFuncSetAttribute(tc_gemm_k, cudaFuncAttributeMaxDynamicSharedMemorySize,
                         SM_TOTAL);

    const int gemm_grid = (NN + 127) / 128;  // 391
    const int warp_grid = (NN + 7) / 8;      // 6250

    // A = x@Wm_top (fp32) ; packed [B fp16 | x fp16] record
    wm_gemm_k<<<dim3(gemm_grid, 2), 256, SM_TOTAL>>>(x, wm, NN);

    // x_new (fp16) = x + sum_e sigmoid(A[c]+B[s]) * x[s]
    edge_agg_k<<<warp_grid, 256>>>(x, esrc);

    // g[c] = sum_e adj[e] * x_new[s]
    gather_k<<<warp_grid, 256>>>(adj, esrc);

    // out = g @ weight + bias
    tc_gemm_k<<<gemm_grid, 256, SM_TOTAL>>>((const float*)pg, weight, bias, out, NN);
}